// round 13
// baseline (speedup 1.0000x reference)
#include <cuda_runtime.h>
#include <cuda_bf16.h>
#include <math.h>

#define TT   256
#define BB   128
#define DD   1024
#define HH   1024
#define DH   2048
#define N4H  4096
#define BH   (BB*HH)
#define NBLK 128

typedef unsigned long long ull;
typedef unsigned int uint;

// Scratch (device globals — no allocation allowed)
__device__ float g_pre[(size_t)TT * BB * N4H];        // x-projection + bias, gate-major cols
__device__ float g_c[BH];                              // cell state [b, j]
__device__ __nv_bfloat16 g_hhi[2][BH];                 // h split-high, ping-pong [buf][b][k]
__device__ __nv_bfloat16 g_hlo[2][BH];                 // h split-low
__device__ __nv_bfloat16 g_whi[(size_t)N4H * HH];      // Wh split-high, block-ordered rows
__device__ __nv_bfloat16 g_wlo[(size_t)N4H * HH];      // Wh split-low
__device__ __nv_bfloat16 g_xhi[(size_t)TT * BB * DD];  // X split-high [T*B][D]
__device__ __nv_bfloat16 g_xlo[(size_t)TT * BB * DD];  // X split-low
__device__ __nv_bfloat16 g_wxhi[(size_t)N4H * DD];     // Wx split-high, rows n = gate*1024+j
__device__ __nv_bfloat16 g_wxlo[(size_t)N4H * DD];     // Wx split-low

// grid barrier state
__device__ int g_bar_cnt = 0;
__device__ volatile int g_bar_gen = 0;

__device__ __forceinline__ float sigmoidf_(float x) { return 1.0f / (1.0f + expf(-x)); }

// ---- mma / async helpers ----
__device__ __forceinline__ uint sptr(const void* p) { return (uint)__cvta_generic_to_shared(p); }
__device__ __forceinline__ void ldsm_x4(uint* r, uint addr) {
    asm volatile("ldmatrix.sync.aligned.m8n8.x4.shared.b16 {%0,%1,%2,%3}, [%4];"
        : "=r"(r[0]), "=r"(r[1]), "=r"(r[2]), "=r"(r[3]) : "r"(addr));
}
__device__ __forceinline__ void mma16816(float* c, const uint* a, const uint* b) {
    asm volatile("mma.sync.aligned.m16n8k16.row.col.f32.bf16.bf16.f32 "
        "{%0,%1,%2,%3}, {%4,%5,%6,%7}, {%8,%9}, {%0,%1,%2,%3};"
        : "+f"(c[0]), "+f"(c[1]), "+f"(c[2]), "+f"(c[3])
        : "r"(a[0]), "r"(a[1]), "r"(a[2]), "r"(a[3]), "r"(b[0]), "r"(b[1]));
}
__device__ __forceinline__ void cp16(uint dst, const void* src) {
    asm volatile("cp.async.cg.shared.global [%0], [%1], 16;" :: "r"(dst), "l"(src));
}
#define CP_COMMIT() asm volatile("cp.async.commit_group;" ::: "memory")
#define CP_WAIT(n)  asm volatile("cp.async.wait_group %0;" :: "n"(n) : "memory")

// ============================================================================
// Split kernels: fp32 -> bf16 hi/lo
// ============================================================================
__global__ void split_wh_kernel(
    const float* __restrict__ Wf, const float* __restrict__ Wi,
    const float* __restrict__ Wg, const float* __restrict__ Wo)
{
    int idx = blockIdx.x * 256 + threadIdx.x;
    int k = idx & 1023;
    int n = idx >> 10;
    int jblk = n >> 5, rem = n & 31, gate = rem >> 3, jl = rem & 7;
    const float* Wt = (gate == 0) ? Wf : (gate == 1) ? Wi : (gate == 2) ? Wg : Wo;
    float w = Wt[(size_t)(jblk * 8 + jl) * DH + DD + k];
    __nv_bfloat16 hi = __float2bfloat16(w);
    g_whi[idx] = hi;
    g_wlo[idx] = __float2bfloat16(w - __bfloat162float(hi));
}

__global__ void split_wx_kernel(
    const float* __restrict__ Wf, const float* __restrict__ Wi,
    const float* __restrict__ Wg, const float* __restrict__ Wo)
{
    int idx = blockIdx.x * 256 + threadIdx.x;      // 0 .. 4096*1024-1
    int k = idx & 1023;
    int n = idx >> 10;                             // n = gate*1024 + j (g_pre col order)
    int gate = n >> 10, j = n & 1023;
    const float* Wt = (gate == 0) ? Wf : (gate == 1) ? Wi : (gate == 2) ? Wg : Wo;
    float w = Wt[(size_t)j * DH + k];              // x-part cols [0, D)
    __nv_bfloat16 hi = __float2bfloat16(w);
    g_wxhi[idx] = hi;
    g_wxlo[idx] = __float2bfloat16(w - __bfloat162float(hi));
}

__global__ void split_x_kernel(const float* __restrict__ X) {
    size_t idx = (size_t)blockIdx.x * 256 + threadIdx.x;   // 0 .. T*B*D-1
    float v = X[idx];
    __nv_bfloat16 hi = __float2bfloat16(v);
    g_xhi[idx] = hi;
    g_xlo[idx] = __float2bfloat16(v - __bfloat162float(hi));
}

// ============================================================================
// Pre-GEMM (tensor core, split-3): g_pre[32768, 4096] = X @ Wx^T + bias
// (unchanged from round 12 — tensor 56%, ~1.1 ms)
// ============================================================================
#define PKC     32
#define PPITCH  40
#define PSTG    (128*PPITCH)             // 5120 bf16 per stage slab
#define PA_HI   0                        // [3][128][40]
#define PA_LO   (3*PSTG)                 // 15360
#define PB_HI   (6*PSTG)                 // 30720
#define PB_LO   (9*PSTG)                 // 46080
#define PBIAS   (12*PSTG)                // 61440 (128 floats)
#define PRE_SMEM_BYTES (PBIAS*2 + 128*4) // 123392 B

__global__ __launch_bounds__(256) void pre_gemm_bf16_kernel(
    const float* __restrict__ bf, const float* __restrict__ bi,
    const float* __restrict__ bg, const float* __restrict__ bo)
{
    extern __shared__ __nv_bfloat16 smb[];
    const int tid  = threadIdx.x;
    const int nb   = blockIdx.x;            // 0..31
    const int mb   = blockIdx.y;            // 0..255
    const int wid  = tid >> 5, lane = tid & 31;
    const int wm   = wid & 3;               // m-tile rows wm*32..+31
    const int wn   = wid >> 2;              // n-tile cols wn*64..+63

    float* biasS = (float*)&smb[PBIAS];
    if (tid < 128) {
        int gate = nb >> 3;
        const float* bt = (gate == 0) ? bf : (gate == 1) ? bi : (gate == 2) ? bg : bo;
        biasS[tid] = bt[(nb & 7) * 128 + tid];
    }

    const int ar  = tid >> 1;               // 0..127
    const int ks0 = (tid & 1) * 16;
    const size_t asrc = (size_t)(mb * 128 + ar) * DD + ks0;
    const size_t bsrc = (size_t)(nb * 128 + ar) * DD + ks0;

#define PRE_ISSUE(c, s) do {                                                      \
    size_t ko = (size_t)(c) * PKC;                                                \
    uint da = sptr(&smb[PA_HI + (s)*PSTG + ar*PPITCH + ks0]);                     \
    uint db = sptr(&smb[PB_HI + (s)*PSTG + ar*PPITCH + ks0]);                     \
    cp16(da,                         &g_xhi[asrc + ko]);                          \
    cp16(da + 16,                    &g_xhi[asrc + ko + 8]);                      \
    cp16(da + (PA_LO-PA_HI)*2,       &g_xlo[asrc + ko]);                          \
    cp16(da + (PA_LO-PA_HI)*2 + 16,  &g_xlo[asrc + ko + 8]);                      \
    cp16(db,                         &g_wxhi[bsrc + ko]);                         \
    cp16(db + 16,                    &g_wxhi[bsrc + ko + 8]);                     \
    cp16(db + (PB_LO-PB_HI)*2,       &g_wxlo[bsrc + ko]);                         \
    cp16(db + (PB_LO-PB_HI)*2 + 16,  &g_wxlo[bsrc + ko + 8]);                     \
} while (0)

    float acc[2][8][4];
#pragma unroll
    for (int mt = 0; mt < 2; mt++)
#pragma unroll
        for (int n8 = 0; n8 < 8; n8++)
#pragma unroll
            for (int i = 0; i < 4; i++) acc[mt][n8][i] = 0.0f;

    const int lrowA = (lane & 7) + ((lane >> 3) & 1) * 8;
    const int lkA   = (lane >> 4) * 8;
    const int gB    = lane >> 3;
    const int lrowB = ((gB >> 1) & 1) * 8 + (lane & 7);
    const int lkB   = (gB & 1) * 8;

    PRE_ISSUE(0, 0); CP_COMMIT();
    PRE_ISSUE(1, 1); CP_COMMIT();

    for (int c = 0; c < DD / PKC; c++) {
        CP_WAIT(1);
        __syncthreads();
        const int stg = c % 3;
#pragma unroll
        for (int k16 = 0; k16 < 2; k16++) {
            uint ahi[2][4], alo[2][4], bh[4][4], bl[4][4];
#pragma unroll
            for (int mt = 0; mt < 2; mt++) {
                int r = wm * 32 + mt * 16 + lrowA;
                int kk = k16 * 16 + lkA;
                ldsm_x4(ahi[mt], sptr(&smb[PA_HI + stg*PSTG + r*PPITCH + kk]));
                ldsm_x4(alo[mt], sptr(&smb[PA_LO + stg*PSTG + r*PPITCH + kk]));
            }
#pragma unroll
            for (int g = 0; g < 4; g++) {
                int r = wn * 64 + g * 16 + lrowB;
                int kk = k16 * 16 + lkB;
                ldsm_x4(bh[g], sptr(&smb[PB_HI + stg*PSTG + r*PPITCH + kk]));
                ldsm_x4(bl[g], sptr(&smb[PB_LO + stg*PSTG + r*PPITCH + kk]));
            }
#pragma unroll
            for (int g = 0; g < 4; g++)
#pragma unroll
                for (int mt = 0; mt < 2; mt++)
#pragma unroll
                    for (int nt = 0; nt < 2; nt++)
                        mma16816(acc[mt][g*2+nt], ahi[mt], &bh[g][nt*2]);
#pragma unroll
            for (int g = 0; g < 4; g++)
#pragma unroll
                for (int mt = 0; mt < 2; mt++)
#pragma unroll
                    for (int nt = 0; nt < 2; nt++)
                        mma16816(acc[mt][g*2+nt], ahi[mt], &bl[g][nt*2]);
#pragma unroll
            for (int g = 0; g < 4; g++)
#pragma unroll
                for (int mt = 0; mt < 2; mt++)
#pragma unroll
                    for (int nt = 0; nt < 2; nt++)
                        mma16816(acc[mt][g*2+nt], alo[mt], &bh[g][nt*2]);
        }
        if (c + 2 < DD / PKC) PRE_ISSUE(c + 2, (c + 2) % 3);
        CP_COMMIT();
    }

#pragma unroll
    for (int mt = 0; mt < 2; mt++)
#pragma unroll
        for (int g = 0; g < 4; g++)
#pragma unroll
            for (int nt = 0; nt < 2; nt++) {
                int r  = wm * 32 + mt * 16 + (lane >> 2);
                int cl = wn * 64 + g * 16 + nt * 8 + (lane & 3) * 2;
                float b0 = biasS[cl], b1 = biasS[cl + 1];
                float* d0 = &g_pre[(size_t)(mb * 128 + r) * N4H + nb * 128 + cl];
                float* d1 = &g_pre[(size_t)(mb * 128 + r + 8) * N4H + nb * 128 + cl];
                d0[0] = acc[mt][g*2+nt][0] + b0;
                d0[1] = acc[mt][g*2+nt][1] + b1;
                d1[0] = acc[mt][g*2+nt][2] + b0;
                d1[1] = acc[mt][g*2+nt][3] + b1;
            }
#undef PRE_ISSUE
}

// ============================================================================
// Persistent recurrence kernel v6: 128 blocks x 512 threads (16 warps,
// 4/SMSP for latency hiding). Warp tile m16 x n16. Weights SMEM-resident,
// h via 4-stage cp.async, grid barrier between steps.
// ============================================================================
#define NTH     512
#define KC      32
#define APITCH  40
#define WPITCH  1032
#define OFFW_HI 0                          // [32][1032]
#define OFFW_LO (32*WPITCH)                // 33024
#define OFFA_HI (2*32*WPITCH)              // 66048  [4][128][40]
#define OFFA_LO (OFFA_HI + 4*128*APITCH)   // 86528
#define SM_TOT  (OFFA_LO + 4*128*APITCH)   // 107008 bf16
#define PERSIST_SMEM_BYTES (SM_TOT * 2)    // 214016 B

__device__ __forceinline__ void grid_barrier() {
    __syncthreads();
    if (threadIdx.x == 0) {
        __threadfence();
        int gen = g_bar_gen;
        if (atomicAdd(&g_bar_cnt, 1) == NBLK - 1) {
            atomicExch(&g_bar_cnt, 0);
            __threadfence();
            g_bar_gen = gen + 1;
        } else {
            while (g_bar_gen == gen) __nanosleep(40);
            __threadfence();
        }
    }
    __syncthreads();
}

__global__ __launch_bounds__(NTH) void lstm_persist_kernel(float* __restrict__ out,
                                                           int write_state)
{
    extern __shared__ __nv_bfloat16 smb[];

    const int tid  = threadIdx.x;
    const int blk  = blockIdx.x;
    const int j0   = blk * 8;
    const int wid  = tid >> 5, lane = tid & 31;
    const int wm   = wid >> 1;          // 0..7 : m-tile rows wm*16..+15
    const int wn   = wid & 1;           // 0..1 : n-tile cols wn*16..+15

    // weights -> smem once
    for (int i = tid; i < 32 * 128; i += NTH) {
        int r = i >> 7, c8 = (i & 127) * 8;
        *(uint4*)&smb[OFFW_HI + r*WPITCH + c8] = *(const uint4*)&g_whi[((size_t)blk*32 + r)*HH + c8];
        *(uint4*)&smb[OFFW_LO + r*WPITCH + c8] = *(const uint4*)&g_wlo[((size_t)blk*32 + r)*HH + c8];
    }
    __syncthreads();

    // proven ldsm lane mappings
    const int lrowA = (lane & 7) + ((lane >> 3) & 1) * 8;
    const int lkA   = (lane >> 4) * 8;
    const int gB    = lane >> 3;
    const int lrowB = wn * 16 + ((gB >> 1) & 1) * 8 + (lane & 7);
    const int lkB   = (gB & 1) * 8;

    // A staging: 4 threads/row, one 16B cp per array per chunk
    const int ar0 = tid >> 2;            // 0..127
    const int as0 = (tid & 3) * 8;       // bf16 offset in chunk

    for (int t = 0; t < TT; t++) {
        const float* preb = g_pre + (size_t)t * BB * N4H;
        float pr[2][4];
        float cold[2];
#pragma unroll
        for (int pp = 0; pp < 2; pp++) {
            int idx = tid + pp * NTH;
            int b   = idx >> 3;
            int jl  = idx & 7;
#pragma unroll
            for (int g = 0; g < 4; g++)
                pr[pp][g] = preb[(size_t)b * N4H + g*1024 + j0 + jl];
            cold[pp] = (t > 0) ? g_c[b * HH + j0 + jl] : 0.0f;
        }

        float acc[2][4];
#pragma unroll
        for (int nt = 0; nt < 2; nt++)
#pragma unroll
            for (int i = 0; i < 4; i++) acc[nt][i] = 0.0f;

        if (t > 0) {
            const __nv_bfloat16* hsrc_hi = g_hhi[t & 1];
            const __nv_bfloat16* hsrc_lo = g_hlo[t & 1];

#define PST_ISSUE(c, s) do {                                                        \
    int ko = (c) * KC + as0;                                                        \
    uint d0 = sptr(&smb[OFFA_HI + ((s)*128 + ar0) * APITCH + as0]);                 \
    cp16(d0,                        &hsrc_hi[(size_t)ar0 * HH + ko]);               \
    cp16(d0 + (OFFA_LO-OFFA_HI)*2,  &hsrc_lo[(size_t)ar0 * HH + ko]);               \
} while (0)

            PST_ISSUE(0, 0); CP_COMMIT();
            PST_ISSUE(1, 1); CP_COMMIT();
            PST_ISSUE(2, 2); CP_COMMIT();

            for (int kc = 0; kc < HH / KC; kc++) {
                CP_WAIT(2);
                __syncthreads();
                const int stg = kc & 3;
#pragma unroll
                for (int k16 = 0; k16 < 2; k16++) {
                    uint ahi[4], alo[4], bhi[4], blo[4];
                    {
                        int r = wm * 16 + lrowA;
                        int kk = k16 * 16 + lkA;
                        ldsm_x4(ahi, sptr(&smb[OFFA_HI + (stg*128 + r) * APITCH + kk]));
                        ldsm_x4(alo, sptr(&smb[OFFA_LO + (stg*128 + r) * APITCH + kk]));
                    }
                    {
                        int kk = kc * KC + k16 * 16 + lkB;
                        ldsm_x4(bhi, sptr(&smb[OFFW_HI + lrowB * WPITCH + kk]));
                        ldsm_x4(blo, sptr(&smb[OFFW_LO + lrowB * WPITCH + kk]));
                    }
#pragma unroll
                    for (int nt = 0; nt < 2; nt++)
                        mma16816(acc[nt], ahi, &bhi[nt*2]);
#pragma unroll
                    for (int nt = 0; nt < 2; nt++)
                        mma16816(acc[nt], ahi, &blo[nt*2]);
#pragma unroll
                    for (int nt = 0; nt < 2; nt++)
                        mma16816(acc[nt], alo, &bhi[nt*2]);
                }
                int nc = kc + 3;
                if (nc < HH / KC) PST_ISSUE(nc, nc & 3);
                CP_COMMIT();
            }
#undef PST_ISSUE
        }

        // write C frags to smem overlay
        float* Gs = (float*)&smb[OFFA_HI];    // [128][33] = 16.9 KB
        __syncthreads();
#pragma unroll
        for (int nt = 0; nt < 2; nt++) {
            int r = wm * 16 + (lane >> 2);
            int c = wn * 16 + nt * 8 + (lane & 3) * 2;
            Gs[r * 33 + c]           = acc[nt][0];
            Gs[r * 33 + c + 1]       = acc[nt][1];
            Gs[(r + 8) * 33 + c]     = acc[nt][2];
            Gs[(r + 8) * 33 + c + 1] = acc[nt][3];
        }
        __syncthreads();

        // fused cell update: 2 (b, jl) pairs per thread
        __nv_bfloat16* hdst_hi = g_hhi[(t + 1) & 1];
        __nv_bfloat16* hdst_lo = g_hlo[(t + 1) & 1];
#pragma unroll
        for (int pp = 0; pp < 2; pp++) {
            int idx = tid + pp * NTH;
            int b   = idx >> 3;
            int jl  = idx & 7;
            float fg = sigmoidf_(Gs[b*33 + jl]       + pr[pp][0]);
            float ig = sigmoidf_(Gs[b*33 + 8  + jl]  + pr[pp][1]);
            float gv = tanhf   (Gs[b*33 + 16 + jl]   + pr[pp][2]);
            float og = sigmoidf_(Gs[b*33 + 24 + jl]  + pr[pp][3]);
            int cidx   = b * HH + j0 + jl;
            float cnew = fg * cold[pp] + ig * gv;
            float h    = og * tanhf(cnew);
            g_c[cidx] = cnew;
            __nv_bfloat16 hh = __float2bfloat16(h);
            hdst_hi[cidx] = hh;
            hdst_lo[cidx] = __float2bfloat16(h - __bfloat162float(hh));
            out[(size_t)t * BH + cidx] = h;
            if (t == TT - 1 && write_state) {
                out[(size_t)TT * BH + cidx]      = h;       // hx
                out[(size_t)TT * BH + BH + cidx] = cnew;    // cx
            }
        }

        if (t < TT - 1) grid_barrier();
    }
}

extern "C" void kernel_launch(void* const* d_in, const int* in_sizes, int n_in,
                              void* d_out, int out_size) {
    const float* X  = (const float*)d_in[0];
    const float* Wf = (const float*)d_in[1];
    const float* bf = (const float*)d_in[2];
    const float* Wi = (const float*)d_in[3];
    const float* bi = (const float*)d_in[4];
    const float* Wg = (const float*)d_in[5];
    const float* bg = (const float*)d_in[6];
    const float* Wo = (const float*)d_in[7];
    const float* bo = (const float*)d_in[8];
    float* out = (float*)d_out;

    cudaFuncSetAttribute(lstm_persist_kernel,
                         cudaFuncAttributeMaxDynamicSharedMemorySize, PERSIST_SMEM_BYTES);
    cudaFuncSetAttribute(pre_gemm_bf16_kernel,
                         cudaFuncAttributeMaxDynamicSharedMemorySize, PRE_SMEM_BYTES);

    // 0) fp32 -> bf16 hi/lo splits
    split_wh_kernel<<<(N4H * HH) / 256, 256>>>(Wf, Wi, Wg, Wo);
    split_wx_kernel<<<(N4H * DD) / 256, 256>>>(Wf, Wi, Wg, Wo);
    split_x_kernel<<<(TT * BB * DD) / 256, 256>>>(X);

    // 1) time-parallel input projection (+bias), tensor-core split-3
    dim3 pgrid(N4H / 128, (TT * BB) / 128);
    pre_gemm_bf16_kernel<<<pgrid, 256, PRE_SMEM_BYTES>>>(bf, bi, bg, bo);

    // 2) whole recurrence in ONE persistent kernel (16 warps/SM)
    int ws = (out_size >= TT * BH + 2 * BH) ? 1 : 0;
    lstm_persist_kernel<<<NBLK, NTH, PERSIST_SMEM_BYTES>>>(out, ws);
}